// round 12
// baseline (speedup 1.0000x reference)
#include <cuda_runtime.h>
#include <cuda_fp16.h>
#include <cstdint>

// ============================================================================
// OrthogonalTransform: Y = X @ R, X viewed as (M=524288, 128), R 128x128.
// Single-pass fp16 HMMA, warp-specialized, B-IN-REGISTERS:
//   - 8 consumer warps: ldmatrix + mma + STG. B fragments (64 regs) loaded
//     once before the persistent loop -> zero B smem traffic in mainloop.
//   - 4 producer warps: LDG.128 x16 up-front -> cvt fp16 -> STS.
// CTA tile 64x128, warp tile 32x32. 5-deep A smem ring (B pack smem reused
// as ring storage after init). 1 CTA/SM (higher regs), named-barrier ring.
// ============================================================================

#define THREADS 384
#define NCONS 256              // consumer threads (warps 0-7)
#define ABUF_BYTES 16384       // 64 rows x 128 fp16 cols (256B/row)
#define RING 5
#define SMEM_TOTAL (RING * ABUF_BYTES)   // 80 KB; B pack aliases bufs 0-1

__device__ __forceinline__ uint32_t smem_u32(const void* p) {
    uint32_t a;
    asm("{ .reg .u64 t; cvta.to.shared.u64 t, %1; cvt.u32.u64 %0, t; }"
        : "=r"(a) : "l"(p));
    return a;
}

__device__ __forceinline__ uint32_t h2u(__half2 h) {
    return *reinterpret_cast<uint32_t*>(&h);
}

// Row r holds 16 chunks of 16B; chunk j at (j&8) | ((j^r)&7).
// Conflict-free for row-major STS and 8-row ldmatrix.
__device__ __forceinline__ uint32_t swz(int row, int chunk) {
    return (uint32_t)((chunk & 8) | ((chunk ^ row) & 7));
}

__device__ __forceinline__ void mma_f16(float* d, const uint32_t* a,
                                        uint32_t b0, uint32_t b1) {
    asm volatile(
        "mma.sync.aligned.m16n8k16.row.col.f32.f16.f16.f32 "
        "{%0,%1,%2,%3}, {%4,%5,%6,%7}, {%8,%9}, {%0,%1,%2,%3};"
        : "+f"(d[0]), "+f"(d[1]), "+f"(d[2]), "+f"(d[3])
        : "r"(a[0]), "r"(a[1]), "r"(a[2]), "r"(a[3]), "r"(b0), "r"(b1));
}

__device__ __forceinline__ void ldmatrix4(uint32_t* a, uint32_t addr) {
    asm volatile(
        "ldmatrix.sync.aligned.m8n8.x4.shared.b16 {%0,%1,%2,%3}, [%4];"
        : "=r"(a[0]), "=r"(a[1]), "=r"(a[2]), "=r"(a[3]) : "r"(addr));
}

// full[s] = barrier 1+s (producers arrive, consumers sync)
// empty[s] = barrier 1+RING+s (consumers arrive, producers sync)
__device__ __forceinline__ void bar_arrive(int id) {
    asm volatile("bar.arrive %0, %1;" :: "r"(id), "r"(THREADS) : "memory");
}
__device__ __forceinline__ void bar_wait(int id) {
    asm volatile("bar.sync %0, %1;" :: "r"(id), "r"(THREADS) : "memory");
}

__global__ void __launch_bounds__(THREADS, 1)
OrthogonalTransform_kernel(const float* __restrict__ x,
                           const float* __restrict__ rot,
                           float* __restrict__ out,
                           int num_tiles) {
    extern __shared__ char smem[];
    const uint32_t smem_base = smem_u32(smem);
    const int tid = threadIdx.x;
    const int lane = tid & 31;

    // ---- Init 1: all threads pack B = R fragments (fp16) into smem ----
    // (transient; this region is reused as A ring buffers afterwards)
    // Entry (ks, nt, lane): uint2 = {k pair (k0,k0+1), (k0+8,k0+9)}.
    // Lane holds n = nt*8 + lane/4, k0 = ks*16 + (lane%4)*2.
    uint2* bp = reinterpret_cast<uint2*>(smem);
    for (int e = tid; e < 4096; e += THREADS) {   // 384 = 12*32: e&31 == lane
        int le = e & 31;
        int nt = (e >> 5) & 15;
        int ks = e >> 9;
        int n  = nt * 8 + (le >> 2);
        int k0 = ks * 16 + (le & 3) * 2;
        __half2 h0 = __floats2half2_rn(rot[k0 * 128 + n], rot[(k0 + 1) * 128 + n]);
        __half2 h1 = __floats2half2_rn(rot[(k0 + 8) * 128 + n], rot[(k0 + 9) * 128 + n]);
        bp[e] = make_uint2(h2u(h0), h2u(h1));
    }
    __syncthreads();

    // ---- Init 2: consumers pull their B fragments into registers ----
    const int wid = tid >> 5;
    const int ngrp = wid & 3;
    uint2 breg[8][4];
    if (tid < NCONS) {
        #pragma unroll
        for (int ks = 0; ks < 8; ks++)
            #pragma unroll
            for (int ni = 0; ni < 4; ni++)
                breg[ks][ni] = bp[(ks * 16 + ngrp * 4 + ni) * 32 + lane];
    }
    __syncthreads();   // B pack fully consumed; ring may overwrite it now

    if (tid >= NCONS) {
        // ==================== PRODUCER (warps 8-11) ====================
        const int ptid = tid - NCONS;           // 0..127
        const int chunkA = (ptid & 31) >> 1;
        const int halfA  = ptid & 1;
        const int rbase  = ptid >> 5;           // row = i*4 + rbase

        int s = 0, it = 0;
        for (int tile = blockIdx.x; tile < num_tiles; tile += gridDim.x, ++it) {
            const float4* src =
                reinterpret_cast<const float4*>(x + (size_t)tile * 8192);
            // Issue ALL 16 LDG.128 before waiting (max DRAM overlap)
            float4 pf[16];
            #pragma unroll
            for (int i = 0; i < 16; i++) pf[i] = src[i * 128 + ptid];

            if (it >= RING) bar_wait(1 + RING + s);   // wait empty[s]

            const uint32_t Ab = (uint32_t)(s * ABUF_BYTES);
            #pragma unroll
            for (int i = 0; i < 16; i++) {
                int row = i * 4 + rbase;
                __half2 h01 = __floats2half2_rn(pf[i].x, pf[i].y);
                __half2 h23 = __floats2half2_rn(pf[i].z, pf[i].w);
                uint32_t off = Ab + row * 256 + (swz(row, chunkA) << 4)
                             + (halfA << 3);
                *reinterpret_cast<uint2*>(smem + off) =
                    make_uint2(h2u(h01), h2u(h23));
            }
            asm volatile("membar.cta;" ::: "memory");
            bar_arrive(1 + s);                   // full[s]
            if (++s == RING) s = 0;
        }
    } else {
        // ==================== CONSUMER (warps 0-7) ====================
        const int mgrp = wid >> 2;              // 0..1 : rows mgrp*32 + mi*16
        const int tq = lane >> 2;
        const int tr = lane & 3;
        const int g_roff = ((lane >> 3) & 1) << 3;
        const int g_coff = lane >> 4;
        const int g_ri   = lane & 7;

        int s = 0;
        for (int tile = blockIdx.x; tile < num_tiles; tile += gridDim.x) {
            bar_wait(1 + s);                     // full[s]
            const uint32_t Abase = smem_base + (uint32_t)(s * ABUF_BYTES);

            float acc[2][4][4];
            #pragma unroll
            for (int mi = 0; mi < 2; mi++)
                #pragma unroll
                for (int ni = 0; ni < 4; ni++)
                    #pragma unroll
                    for (int j = 0; j < 4; j++) acc[mi][ni][j] = 0.0f;

            #pragma unroll
            for (int ks = 0; ks < 8; ks++) {
                uint32_t a[2][4];
                #pragma unroll
                for (int mi = 0; mi < 2; mi++) {
                    int row = mgrp * 32 + mi * 16 + g_roff + g_ri;
                    int chunk = 2 * ks + g_coff;
                    ldmatrix4(a[mi],
                              Abase + row * 256 + (swz(row, chunk) << 4));
                }
                #pragma unroll
                for (int ni = 0; ni < 4; ni++)
                    #pragma unroll
                    for (int mi = 0; mi < 2; mi++)
                        mma_f16(acc[mi][ni], a[mi],
                                breg[ks][ni].x, breg[ks][ni].y);
            }

            // All smem reads of buf s complete (their MMAs issued).
            bar_arrive(1 + RING + s);            // empty[s] — overlap epilogue
            if (++s == RING) s = 0;

            // ---- Epilogue: C fragments -> GMEM ----
            float* ot = out + (size_t)tile * 8192;
            #pragma unroll
            for (int mi = 0; mi < 2; mi++) {
                int r0 = mgrp * 32 + mi * 16 + tq;
                #pragma unroll
                for (int ni = 0; ni < 4; ni++) {
                    int c = ngrp * 32 + ni * 8 + tr * 2;
                    *reinterpret_cast<float2*>(ot + r0 * 128 + c) =
                        make_float2(acc[mi][ni][0], acc[mi][ni][1]);
                    *reinterpret_cast<float2*>(ot + (r0 + 8) * 128 + c) =
                        make_float2(acc[mi][ni][2], acc[mi][ni][3]);
                }
            }
        }
    }
}

extern "C" void kernel_launch(void* const* d_in, const int* in_sizes, int n_in,
                              void* d_out, int out_size) {
    const float* x = (const float*)d_in[0];
    const float* rot = (const float*)d_in[1];
    float* out = (float*)d_out;

    int num_tiles = in_sizes[0] / 8192;   // 64x128 fp32 per tile

    static int num_sms = 0;
    if (num_sms == 0) {
        if (cudaDeviceGetAttribute(&num_sms, cudaDevAttrMultiProcessorCount, 0)
                != cudaSuccess || num_sms <= 0)
            num_sms = 148;
        cudaFuncSetAttribute(OrthogonalTransform_kernel,
                             cudaFuncAttributeMaxDynamicSharedMemorySize,
                             SMEM_TOTAL);
    }

    int grid = num_sms < num_tiles ? num_sms : num_tiles;
    OrthogonalTransform_kernel<<<grid, THREADS, SMEM_TOTAL>>>(x, rot, out,
                                                              num_tiles);
}

// round 15
// speedup vs baseline: 1.0754x; 1.0754x over previous
#include <cuda_runtime.h>
#include <cuda_fp16.h>
#include <cstdint>

// ============================================================================
// OrthogonalTransform: Y = X @ R, X viewed as (M=524288, 128), R 128x128.
// Single-pass fp16 HMMA, warp-specialized, cp.async producer:
//   - 4 producer warps: cp.async.cg gmem -> fp32 staging smem (3-deep ring,
//     issued ~3 tiles ahead, zero register stalls), then LDS.128 -> cvt fp16
//     -> STS into the fp16 A ring. DRAM requests stream steadily.
//   - 8 consumer warps: ldmatrix + HMMA + STG; B fragments in registers.
// CTA tile 64x128, warp tile 32x32. fp16 ring RING=4, staging D=3. 1 CTA/SM.
// ============================================================================

#define THREADS 384
#define NCONS 256                  // consumer threads (warps 0-7)
#define ABUF_BYTES 16384           // fp16 tile: 64 rows x 256B
#define RING 4
#define STAGE_BYTES 32768          // fp32 tile: 64 rows x 512B
#define DEPTH 3
#define SMEM_STAGE (RING * ABUF_BYTES)             // 65536
#define SMEM_TOTAL (SMEM_STAGE + DEPTH * STAGE_BYTES)  // 160 KB

__device__ __forceinline__ uint32_t smem_u32(const void* p) {
    uint32_t a;
    asm("{ .reg .u64 t; cvta.to.shared.u64 t, %1; cvt.u32.u64 %0, t; }"
        : "=r"(a) : "l"(p));
    return a;
}

__device__ __forceinline__ uint32_t h2u(__half2 h) {
    return *reinterpret_cast<uint32_t*>(&h);
}

// Row r holds 16 chunks of 16B; chunk j at (j&8) | ((j^r)&7).
// Conflict-free for row-major STS and 8-row ldmatrix.
__device__ __forceinline__ uint32_t swz(int row, int chunk) {
    return (uint32_t)((chunk & 8) | ((chunk ^ row) & 7));
}

__device__ __forceinline__ void mma_f16(float* d, const uint32_t* a,
                                        uint32_t b0, uint32_t b1) {
    asm volatile(
        "mma.sync.aligned.m16n8k16.row.col.f32.f16.f16.f32 "
        "{%0,%1,%2,%3}, {%4,%5,%6,%7}, {%8,%9}, {%0,%1,%2,%3};"
        : "+f"(d[0]), "+f"(d[1]), "+f"(d[2]), "+f"(d[3])
        : "r"(a[0]), "r"(a[1]), "r"(a[2]), "r"(a[3]), "r"(b0), "r"(b1));
}

__device__ __forceinline__ void ldmatrix4(uint32_t* a, uint32_t addr) {
    asm volatile(
        "ldmatrix.sync.aligned.m8n8.x4.shared.b16 {%0,%1,%2,%3}, [%4];"
        : "=r"(a[0]), "=r"(a[1]), "=r"(a[2]), "=r"(a[3]) : "r"(addr));
}

// full[s] = barrier 1+s (producers arrive, consumers sync)
// empty[s] = barrier 1+RING+s (consumers arrive, producers sync)
__device__ __forceinline__ void bar_arrive(int id) {
    asm volatile("bar.arrive %0, %1;" :: "r"(id), "r"(THREADS) : "memory");
}
__device__ __forceinline__ void bar_wait(int id) {
    asm volatile("bar.sync %0, %1;" :: "r"(id), "r"(THREADS) : "memory");
}

__device__ __forceinline__ void cp16(uint32_t smem_dst, const void* gmem_src) {
    asm volatile("cp.async.cg.shared.global [%0], [%1], 16;"
                 :: "r"(smem_dst), "l"(gmem_src) : "memory");
}
__device__ __forceinline__ void cp_commit() {
    asm volatile("cp.async.commit_group;" ::: "memory");
}
template <int N>
__device__ __forceinline__ void cp_wait() {
    asm volatile("cp.async.wait_group %0;" :: "n"(N) : "memory");
}

__global__ void __launch_bounds__(THREADS, 1)
OrthogonalTransform_kernel(const float* __restrict__ x,
                           const float* __restrict__ rot,
                           float* __restrict__ out,
                           int num_tiles) {
    extern __shared__ char smem[];
    const uint32_t smem_base = smem_u32(smem);
    const int tid = threadIdx.x;
    const int lane = tid & 31;
    const int wid = tid >> 5;

    // ---- Init 1: pack B = R fragments (fp16) into transient smem ----
    // (placed in staging[0] region; consumed before any cp.async lands)
    // Entry (ks, nt, lane): uint2 = {k pair (k0,k0+1), (k0+8,k0+9)}.
    // Lane holds n = nt*8 + lane/4, k0 = ks*16 + (lane%4)*2.
    uint2* bp = reinterpret_cast<uint2*>(smem + SMEM_STAGE);
    for (int e = tid; e < 4096; e += THREADS) {   // 384 = 12*32: e&31 == lane
        int le = e & 31;
        int nt = (e >> 5) & 15;
        int ks = e >> 9;
        int n  = nt * 8 + (le >> 2);
        int k0 = ks * 16 + (le & 3) * 2;
        __half2 h0 = __floats2half2_rn(rot[k0 * 128 + n], rot[(k0 + 1) * 128 + n]);
        __half2 h1 = __floats2half2_rn(rot[(k0 + 8) * 128 + n], rot[(k0 + 9) * 128 + n]);
        bp[e] = make_uint2(h2u(h0), h2u(h1));
    }
    __syncthreads();

    // ---- Init 2: consumers pull their B fragments into registers ----
    const int ngrp = wid & 3;
    uint2 breg[8][4];
    if (tid < NCONS) {
        #pragma unroll
        for (int ks = 0; ks < 8; ks++)
            #pragma unroll
            for (int ni = 0; ni < 4; ni++)
                breg[ks][ni] = bp[(ks * 16 + ngrp * 4 + ni) * 32 + lane];
    }
    __syncthreads();   // B pack fully consumed; staging may overwrite it now

    if (tid >= NCONS) {
        // ==================== PRODUCER (warps 8-11) ====================
        const int ptid = tid - NCONS;           // 0..127
        const int chunkA = (ptid & 31) >> 1;
        const int halfA  = ptid & 1;
        const int rbase  = ptid >> 5;           // row = i*4 + rbase

        // Prologue: issue cp.async for the first DEPTH tiles.
        #pragma unroll
        for (int d = 0; d < DEPTH; d++) {
            int t = blockIdx.x + d * gridDim.x;
            if (t < num_tiles) {
                const float* src = x + (size_t)t * 8192;
                uint32_t stg = smem_base + SMEM_STAGE + d * STAGE_BYTES;
                #pragma unroll
                for (int i = 0; i < 16; i++)
                    cp16(stg + (i * 128 + ptid) * 16, src + (i * 128 + ptid) * 4);
            }
            cp_commit();
        }

        int s = 0, j = 0, it = 0;
        for (int tile = blockIdx.x; tile < num_tiles; tile += gridDim.x, ++it) {
            cp_wait<DEPTH - 1>();               // staging[j] data arrived
            if (it >= RING) bar_wait(1 + RING + s);   // wait empty[s]

            const uint32_t stg = smem_base + SMEM_STAGE + j * STAGE_BYTES;
            const uint32_t Ab = (uint32_t)(s * ABUF_BYTES);
            #pragma unroll
            for (int i = 0; i < 16; i++) {
                float4 v = *reinterpret_cast<const float4*>(
                    smem + SMEM_STAGE + j * STAGE_BYTES + (i * 128 + ptid) * 16);
                int row = i * 4 + rbase;
                __half2 h01 = __floats2half2_rn(v.x, v.y);
                __half2 h23 = __floats2half2_rn(v.z, v.w);
                uint32_t off = Ab + row * 256 + (swz(row, chunkA) << 4)
                             + (halfA << 3);
                *reinterpret_cast<uint2*>(smem + off) =
                    make_uint2(h2u(h01), h2u(h23));
            }
            asm volatile("membar.cta;" ::: "memory");
            bar_arrive(1 + s);                   // full[s]

            // Reuse staging[j] for tile t+DEPTH (this thread has consumed
            // exactly the bytes it staged -> per-thread ordering suffices).
            int nt2 = tile + DEPTH * gridDim.x;
            if (nt2 < num_tiles) {
                const float* src = x + (size_t)nt2 * 8192;
                #pragma unroll
                for (int i = 0; i < 16; i++)
                    cp16(stg + (i * 128 + ptid) * 16, src + (i * 128 + ptid) * 4);
            }
            cp_commit();                         // keep group counting uniform

            if (++s == RING) s = 0;
            if (++j == DEPTH) j = 0;
        }
    } else {
        // ==================== CONSUMER (warps 0-7) ====================
        const int mgrp = wid >> 2;              // 0..1 : rows mgrp*32 + mi*16
        const int tq = lane >> 2;
        const int tr = lane & 3;
        const int g_roff = ((lane >> 3) & 1) << 3;
        const int g_coff = lane >> 4;
        const int g_ri   = lane & 7;

        int s = 0;
        for (int tile = blockIdx.x; tile < num_tiles; tile += gridDim.x) {
            bar_wait(1 + s);                     // full[s]
            const uint32_t Abase = smem_base + (uint32_t)(s * ABUF_BYTES);

            float acc[2][4][4];
            #pragma unroll
            for (int mi = 0; mi < 2; mi++)
                #pragma unroll
                for (int ni = 0; ni < 4; ni++)
                    #pragma unroll
                    for (int j2 = 0; j2 < 4; j2++) acc[mi][ni][j2] = 0.0f;

            #pragma unroll
            for (int ks = 0; ks < 8; ks++) {
                uint32_t a[2][4];
                #pragma unroll
                for (int mi = 0; mi < 2; mi++) {
                    int row = mgrp * 32 + mi * 16 + g_roff + g_ri;
                    int chunk = 2 * ks + g_coff;
                    ldmatrix4(a[mi],
                              Abase + row * 256 + (swz(row, chunk) << 4));
                }
                #pragma unroll
                for (int ni = 0; ni < 4; ni++)
                    #pragma unroll
                    for (int mi = 0; mi < 2; mi++)
                        mma_f16(acc[mi][ni], a[mi],
                                breg[ks][ni].x, breg[ks][ni].y);
            }

            // All smem reads of buf s complete (their MMAs issued).
            bar_arrive(1 + RING + s);            // empty[s] — overlap epilogue
            if (++s == RING) s = 0;

            // ---- Epilogue: C fragments -> GMEM ----
            float* ot = out + (size_t)tile * 8192;
            #pragma unroll
            for (int mi = 0; mi < 2; mi++) {
                int r0 = mgrp * 32 + mi * 16 + tq;
                #pragma unroll
                for (int ni = 0; ni < 4; ni++) {
                    int c = ngrp * 32 + ni * 8 + tr * 2;
                    *reinterpret_cast<float2*>(ot + r0 * 128 + c) =
                        make_float2(acc[mi][ni][0], acc[mi][ni][1]);
                    *reinterpret_cast<float2*>(ot + (r0 + 8) * 128 + c) =
                        make_float2(acc[mi][ni][2], acc[mi][ni][3]);
                }
            }
        }
    }
}

extern "C" void kernel_launch(void* const* d_in, const int* in_sizes, int n_in,
                              void* d_out, int out_size) {
    const float* x = (const float*)d_in[0];
    const float* rot = (const float*)d_in[1];
    float* out = (float*)d_out;

    int num_tiles = in_sizes[0] / 8192;   // 64x128 fp32 per tile

    static int num_sms = 0;
    if (num_sms == 0) {
        if (cudaDeviceGetAttribute(&num_sms, cudaDevAttrMultiProcessorCount, 0)
                != cudaSuccess || num_sms <= 0)
            num_sms = 148;
        cudaFuncSetAttribute(OrthogonalTransform_kernel,
                             cudaFuncAttributeMaxDynamicSharedMemorySize,
                             SMEM_TOTAL);
    }

    int grid = num_sms < num_tiles ? num_sms : num_tiles;
    OrthogonalTransform_kernel<<<grid, THREADS, SMEM_TOTAL>>>(x, rot, out,
                                                              num_tiles);
}

// round 16
// speedup vs baseline: 1.1404x; 1.0604x over previous
#include <cuda_runtime.h>
#include <cuda_fp16.h>
#include <cstdint>

// ============================================================================
// OrthogonalTransform: Y = X @ R, X viewed as (M=524288, 128), R 128x128.
// Single-pass fp16 HMMA, warp-specialized, cp.async producer, smem-staged
// coalesced epilogue:
//   - 4 producer warps: cp.async.cg gmem -> fp32 staging (3-deep ring), then
//     LDS.128 -> cvt fp16 -> STS into fp16 A ring (4-deep).
//   - 8 consumer warps: ldmatrix + HMMA (B in registers) -> STS C fragments
//     into rotated smem buffer -> bar -> row-coalesced LDS.128 + STG.128.
// CTA tile 64x128, warp tile 32x32. 1 CTA/SM, 192 KB smem.
// ============================================================================

#define THREADS 384
#define NCONS 256                  // consumer threads (warps 0-7)
#define ABUF_BYTES 16384           // fp16 tile: 64 rows x 256B
#define RING 4
#define STAGE_BYTES 32768          // fp32 tile: 64 rows x 512B
#define DEPTH 3
#define SMEM_STAGE (RING * ABUF_BYTES)                  // 65536
#define SMEM_EPI   (SMEM_STAGE + DEPTH * STAGE_BYTES)   // 163840
#define SMEM_TOTAL (SMEM_EPI + 32768)                   // 196608 (192 KB)

__device__ __forceinline__ uint32_t smem_u32(const void* p) {
    uint32_t a;
    asm("{ .reg .u64 t; cvta.to.shared.u64 t, %1; cvt.u32.u64 %0, t; }"
        : "=r"(a) : "l"(p));
    return a;
}

__device__ __forceinline__ uint32_t h2u(__half2 h) {
    return *reinterpret_cast<uint32_t*>(&h);
}

// fp16 A-tile swizzle: row r, 16B chunk j at (j&8) | ((j^r)&7).
__device__ __forceinline__ uint32_t swz(int row, int chunk) {
    return (uint32_t)((chunk & 8) | ((chunk ^ row) & 7));
}

// Epilogue rotation: row r, float2-chunk cc (0..63) -> rotated chunk.
// Keeps 16-chunk (128B) groups; spreads banks so frag STS is 2-wf minimal
// and row readback is conflict-free.
__device__ __forceinline__ int epi_cc(int r, int cc) {
    return (cc & 48) | ((cc + 4 * (r & 3)) & 15);
}

__device__ __forceinline__ void mma_f16(float* d, const uint32_t* a,
                                        uint32_t b0, uint32_t b1) {
    asm volatile(
        "mma.sync.aligned.m16n8k16.row.col.f32.f16.f16.f32 "
        "{%0,%1,%2,%3}, {%4,%5,%6,%7}, {%8,%9}, {%0,%1,%2,%3};"
        : "+f"(d[0]), "+f"(d[1]), "+f"(d[2]), "+f"(d[3])
        : "r"(a[0]), "r"(a[1]), "r"(a[2]), "r"(a[3]), "r"(b0), "r"(b1));
}

__device__ __forceinline__ void ldmatrix4(uint32_t* a, uint32_t addr) {
    asm volatile(
        "ldmatrix.sync.aligned.m8n8.x4.shared.b16 {%0,%1,%2,%3}, [%4];"
        : "=r"(a[0]), "=r"(a[1]), "=r"(a[2]), "=r"(a[3]) : "r"(addr));
}

// full[s] = barrier 1+s (producers arrive, consumers sync)
// empty[s] = barrier 1+RING+s (consumers arrive, producers sync)
// epilogue barrier = 9 (consumers only, 256 threads)
__device__ __forceinline__ void bar_arrive(int id) {
    asm volatile("bar.arrive %0, %1;" :: "r"(id), "r"(THREADS) : "memory");
}
__device__ __forceinline__ void bar_wait(int id) {
    asm volatile("bar.sync %0, %1;" :: "r"(id), "r"(THREADS) : "memory");
}
__device__ __forceinline__ void bar_cons() {
    asm volatile("bar.sync 9, %0;" :: "r"(NCONS) : "memory");
}

__device__ __forceinline__ void cp16(uint32_t smem_dst, const void* gmem_src) {
    asm volatile("cp.async.cg.shared.global [%0], [%1], 16;"
                 :: "r"(smem_dst), "l"(gmem_src) : "memory");
}
__device__ __forceinline__ void cp_commit() {
    asm volatile("cp.async.commit_group;" ::: "memory");
}
template <int N>
__device__ __forceinline__ void cp_wait() {
    asm volatile("cp.async.wait_group %0;" :: "n"(N) : "memory");
}

__global__ void __launch_bounds__(THREADS, 1)
OrthogonalTransform_kernel(const float* __restrict__ x,
                           const float* __restrict__ rot,
                           float* __restrict__ out,
                           int num_tiles) {
    extern __shared__ char smem[];
    const uint32_t smem_base = smem_u32(smem);
    const int tid = threadIdx.x;
    const int lane = tid & 31;
    const int wid = tid >> 5;

    // ---- Init 1: pack B = R fragments (fp16) into transient smem ----
    // Entry (ks, nt, lane): uint2 = {k pair (k0,k0+1), (k0+8,k0+9)}.
    // Lane holds n = nt*8 + lane/4, k0 = ks*16 + (lane%4)*2.
    uint2* bp = reinterpret_cast<uint2*>(smem + SMEM_STAGE);
    for (int e = tid; e < 4096; e += THREADS) {   // 384 = 12*32: e&31 == lane
        int le = e & 31;
        int nt = (e >> 5) & 15;
        int ks = e >> 9;
        int n  = nt * 8 + (le >> 2);
        int k0 = ks * 16 + (le & 3) * 2;
        __half2 h0 = __floats2half2_rn(rot[k0 * 128 + n], rot[(k0 + 1) * 128 + n]);
        __half2 h1 = __floats2half2_rn(rot[(k0 + 8) * 128 + n], rot[(k0 + 9) * 128 + n]);
        bp[e] = make_uint2(h2u(h0), h2u(h1));
    }
    __syncthreads();

    // ---- Init 2: consumers pull their B fragments into registers ----
    const int ngrp = wid & 3;
    uint2 breg[8][4];
    if (tid < NCONS) {
        #pragma unroll
        for (int ks = 0; ks < 8; ks++)
            #pragma unroll
            for (int ni = 0; ni < 4; ni++)
                breg[ks][ni] = bp[(ks * 16 + ngrp * 4 + ni) * 32 + lane];
    }
    __syncthreads();   // B pack fully consumed; staging may overwrite it now

    if (tid >= NCONS) {
        // ==================== PRODUCER (warps 8-11) ====================
        const int ptid = tid - NCONS;           // 0..127
        const int chunkA = (ptid & 31) >> 1;
        const int halfA  = ptid & 1;
        const int rbase  = ptid >> 5;           // row = i*4 + rbase

        // Prologue: issue cp.async for the first DEPTH tiles.
        #pragma unroll
        for (int d = 0; d < DEPTH; d++) {
            int t = blockIdx.x + d * gridDim.x;
            if (t < num_tiles) {
                const float* src = x + (size_t)t * 8192;
                uint32_t stg = smem_base + SMEM_STAGE + d * STAGE_BYTES;
                #pragma unroll
                for (int i = 0; i < 16; i++)
                    cp16(stg + (i * 128 + ptid) * 16, src + (i * 128 + ptid) * 4);
            }
            cp_commit();
        }

        int s = 0, j = 0, it = 0;
        for (int tile = blockIdx.x; tile < num_tiles; tile += gridDim.x, ++it) {
            cp_wait<DEPTH - 1>();               // staging[j] data arrived
            if (it >= RING) bar_wait(1 + RING + s);   // wait empty[s]

            const uint32_t stg = smem_base + SMEM_STAGE + j * STAGE_BYTES;
            const uint32_t Ab = (uint32_t)(s * ABUF_BYTES);
            #pragma unroll
            for (int i = 0; i < 16; i++) {
                float4 v = *reinterpret_cast<const float4*>(
                    smem + SMEM_STAGE + j * STAGE_BYTES + (i * 128 + ptid) * 16);
                int row = i * 4 + rbase;
                __half2 h01 = __floats2half2_rn(v.x, v.y);
                __half2 h23 = __floats2half2_rn(v.z, v.w);
                uint32_t off = Ab + row * 256 + (swz(row, chunkA) << 4)
                             + (halfA << 3);
                *reinterpret_cast<uint2*>(smem + off) =
                    make_uint2(h2u(h01), h2u(h23));
            }
            asm volatile("membar.cta;" ::: "memory");
            bar_arrive(1 + s);                   // full[s]

            // Reuse staging[j] for tile t+DEPTH (this thread consumed exactly
            // the bytes it staged -> per-thread group ordering suffices).
            int nt2 = tile + DEPTH * gridDim.x;
            if (nt2 < num_tiles) {
                const float* src = x + (size_t)nt2 * 8192;
                #pragma unroll
                for (int i = 0; i < 16; i++)
                    cp16(stg + (i * 128 + ptid) * 16, src + (i * 128 + ptid) * 4);
            }
            cp_commit();                         // keep group counting uniform

            if (++s == RING) s = 0;
            if (++j == DEPTH) j = 0;
        }
    } else {
        // ==================== CONSUMER (warps 0-7) ====================
        const int mgrp = wid >> 2;              // 0..1 : rows mgrp*32 + mi*16
        const int tq = lane >> 2;
        const int tr = lane & 3;
        const int g_roff = ((lane >> 3) & 1) << 3;
        const int g_coff = lane >> 4;
        const int g_ri   = lane & 7;

        int s = 0;
        for (int tile = blockIdx.x; tile < num_tiles; tile += gridDim.x) {
            bar_wait(1 + s);                     // full[s]; also orders
                                                 // epi-LDS(t-1) before STS(t)
            const uint32_t Abase = smem_base + (uint32_t)(s * ABUF_BYTES);

            float acc[2][4][4];
            #pragma unroll
            for (int mi = 0; mi < 2; mi++)
                #pragma unroll
                for (int ni = 0; ni < 4; ni++)
                    #pragma unroll
                    for (int j2 = 0; j2 < 4; j2++) acc[mi][ni][j2] = 0.0f;

            #pragma unroll
            for (int ks = 0; ks < 8; ks++) {
                uint32_t a[2][4];
                #pragma unroll
                for (int mi = 0; mi < 2; mi++) {
                    int row = mgrp * 32 + mi * 16 + g_roff + g_ri;
                    int chunk = 2 * ks + g_coff;
                    ldmatrix4(a[mi],
                              Abase + row * 256 + (swz(row, chunk) << 4));
                }
                #pragma unroll
                for (int ni = 0; ni < 4; ni++)
                    #pragma unroll
                    for (int mi = 0; mi < 2; mi++)
                        mma_f16(acc[mi][ni], a[mi],
                                breg[ks][ni].x, breg[ks][ni].y);
            }

            // All smem reads of buf s complete (their MMAs issued).
            bar_arrive(1 + RING + s);            // empty[s] — overlap epilogue
            if (++s == RING) s = 0;

            // ---- Epilogue A: fragments -> rotated smem buffer ----
            #pragma unroll
            for (int mi = 0; mi < 2; mi++) {
                int r0 = mgrp * 32 + mi * 16 + tq;     // (r0+8)&3 == r0&3
                #pragma unroll
                for (int ni = 0; ni < 4; ni++) {
                    int cc = (ngrp * 32 + ni * 8 + tr * 2) >> 1;
                    uint32_t o = (uint32_t)(SMEM_EPI + (epi_cc(r0, cc) << 3));
                    *reinterpret_cast<float2*>(smem + o + r0 * 512) =
                        make_float2(acc[mi][ni][0], acc[mi][ni][1]);
                    *reinterpret_cast<float2*>(smem + o + (r0 + 8) * 512) =
                        make_float2(acc[mi][ni][2], acc[mi][ni][3]);
                }
            }
            bar_cons();

            // ---- Epilogue B: row-coalesced readback + STG.128 ----
            float* ot = out + (size_t)tile * 8192;
            #pragma unroll
            for (int i = 0; i < 8; i++) {
                int r = i * 8 + wid;
                int ccp = epi_cc(r, 2 * lane);
                float4 v = *reinterpret_cast<const float4*>(
                    smem + SMEM_EPI + r * 512 + (ccp << 3));
                *reinterpret_cast<float4*>(ot + r * 128 + lane * 4) = v;
            }
        }
    }
}

extern "C" void kernel_launch(void* const* d_in, const int* in_sizes, int n_in,
                              void* d_out, int out_size) {
    const float* x = (const float*)d_in[0];
    const float* rot = (const float*)d_in[1];
    float* out = (float*)d_out;

    int num_tiles = in_sizes[0] / 8192;   // 64x128 fp32 per tile

    static int num_sms = 0;
    if (num_sms == 0) {
        if (cudaDeviceGetAttribute(&num_sms, cudaDevAttrMultiProcessorCount, 0)
                != cudaSuccess || num_sms <= 0)
            num_sms = 148;
        cudaFuncSetAttribute(OrthogonalTransform_kernel,
                             cudaFuncAttributeMaxDynamicSharedMemorySize,
                             SMEM_TOTAL);
    }

    int grid = num_sms < num_tiles ? num_sms : num_tiles;
    OrthogonalTransform_kernel<<<grid, THREADS, SMEM_TOTAL>>>(x, rot, out,
                                                              num_tiles);
}